// round 14
// baseline (speedup 1.0000x reference)
#include <cuda_runtime.h>

// QModel_43885975830736 — FINAL (converged; held, 9 identical-binary samples).
//
// Math identity (rel_err 3.071735e-07, bit-stable across 13 runs): wire 8 is
// never acted on by any gate, so its |1> amplitude block remains exactly
// zero through the whole circuit; all gates are unitary and the embedding
// is normalized, hence probs(wire 8) == [1, 0] for every batch row,
// independent of x and weights. The entire workload reduces to writing the
// 1,0,1,0,... pattern into the (16384, 2) fp32 output (128 KB).
//
// Perf: pinned at the graph-replay launch-overhead floor (DRAM 0.0% on
// every run; store traffic invisible). Identical-binary kernel-dur noise
// band: 3.33-3.78us (9 samples) — wider than the gaps between most grid
// shapes, so geometry differences below ~0.4us are unresolvable. Ladder:
//   16x256 one-v8/thread : 3.33-3.78us  <- optimum (best central tendency)
//   32x256 v4+tail       : 3.52us
//   64x128               : 3.65us
//   4x1024               : 3.78us
//   8x128  v8x4/thread   : 4.10us  (dep chain + 38 regs — only clearly
//                                   distinct configuration)
// End-to-end noise band: 4.58-5.18us. All structural alternatives
// (memcpy/memset nodes, multi-node graphs) strictly worse.

__global__ void __launch_bounds__(256, 1)
qmodel_fill8(float* __restrict__ out) {
    unsigned idx = blockIdx.x * 256u + threadIdx.x;
    float* p = out + (size_t)idx * 8u;
    asm volatile(
        "st.global.v8.f32 [%0], {%1, %2, %1, %2, %1, %2, %1, %2};"
        :: "l"(p), "f"(1.0f), "f"(0.0f)
        : "memory");
}

// Guarded fallback for any unexpected out_size.
__global__ void __launch_bounds__(256, 1)
qmodel_fill_guarded(float* __restrict__ out, int n) {
    int i = blockIdx.x * 256 + threadIdx.x;
    if (i < n) out[i] = (i & 1) ? 0.0f : 1.0f;
}

extern "C" void kernel_launch(void* const* d_in, const int* in_sizes, int n_in,
                              void* d_out, int out_size) {
    (void)d_in; (void)in_sizes; (void)n_in;
    if ((out_size & 2047) == 0 && out_size > 0) {
        int threads_total = out_size >> 3;   // one v8 store each
        int blocks = threads_total >> 8;     // /256, exact by the mask check
        qmodel_fill8<<<blocks, 256>>>((float*)d_out);
        return;
    }
    int blocks = (out_size + 255) / 256;
    if (blocks < 1) blocks = 1;
    qmodel_fill_guarded<<<blocks, 256>>>((float*)d_out, out_size);
}

// round 15
// speedup vs baseline: 1.2797x; 1.2797x over previous
#include <cuda_runtime.h>

// QModel_43885975830736 — FINAL (converged; held, 10 identical-binary samples).
//
// Math identity (rel_err 3.071735e-07, bit-stable across 14 runs): wire 8 is
// never acted on by any gate, so its |1> amplitude block remains exactly
// zero through the whole circuit; all gates are unitary and the embedding
// is normalized, hence probs(wire 8) == [1, 0] for every batch row,
// independent of x and weights. The entire workload reduces to writing the
// 1,0,1,0,... pattern into the (16384, 2) fp32 output (128 KB).
//
// Perf: pinned at the graph-replay launch-overhead floor (DRAM 0.0% on
// every run; store traffic invisible). Identical-binary noise bands after
// 10 samples: kernel 3.33-3.84us, end-to-end 4.58-5.86us — environmental
// variance exceeds every geometry effect measured except the R4 dep-chain
// kernel (4.10us). Ladder:
//   16x256 one-v8/thread : 3.33-3.84us  <- optimum (best central tendency)
//   32x256 v4+tail       : 3.52us
//   64x128               : 3.65us
//   4x1024               : 3.78us
//   8x128  v8x4/thread   : 4.10us  (dep chain + 38 regs)
// All structural alternatives (memcpy/memset nodes, multi-node graphs)
// strictly worse on dispatch count.

__global__ void __launch_bounds__(256, 1)
qmodel_fill8(float* __restrict__ out) {
    unsigned idx = blockIdx.x * 256u + threadIdx.x;
    float* p = out + (size_t)idx * 8u;
    asm volatile(
        "st.global.v8.f32 [%0], {%1, %2, %1, %2, %1, %2, %1, %2};"
        :: "l"(p), "f"(1.0f), "f"(0.0f)
        : "memory");
}

// Guarded fallback for any unexpected out_size.
__global__ void __launch_bounds__(256, 1)
qmodel_fill_guarded(float* __restrict__ out, int n) {
    int i = blockIdx.x * 256 + threadIdx.x;
    if (i < n) out[i] = (i & 1) ? 0.0f : 1.0f;
}

extern "C" void kernel_launch(void* const* d_in, const int* in_sizes, int n_in,
                              void* d_out, int out_size) {
    (void)d_in; (void)in_sizes; (void)n_in;
    if ((out_size & 2047) == 0 && out_size > 0) {
        int threads_total = out_size >> 3;   // one v8 store each
        int blocks = threads_total >> 8;     // /256, exact by the mask check
        qmodel_fill8<<<blocks, 256>>>((float*)d_out);
        return;
    }
    int blocks = (out_size + 255) / 256;
    if (blocks < 1) blocks = 1;
    qmodel_fill_guarded<<<blocks, 256>>>((float*)d_out, out_size);
}